// round 3
// baseline (speedup 1.0000x reference)
#include <cuda_runtime.h>
#include <cstdint>
#include <cstddef>

// ---------------------------------------------------------------------------
// BufferAttend1d: B=8, Q=K=4096, DIM_IN=256, KEY_DIM=VAL_DIM=64
//   q = x @ Wk^T + bk ; k = buffer @ Wk^T + bk ; v = buffer @ Wv^T + bv
//   logits = q k^T / 8 ; masked -> -1024 ; probs = softmax ; read = probs @ v
// Output: probs (8*4096*4096 f32) then read (8*4096*64 f32), concatenated.
//
// TF32 mma.sync (RNA). Q fragments live in registers (converted once, reused
// across all k-tiles and both passes). K/V/E are stored in SMEM already
// converted to tf32 bit patterns, so inner loops contain no CVT.
// Two passes over K per q-tile:
//   Pass A: e = keep * exp2(l*log2e/8) (no max-subtract: logits provably
//           small; masked probs exactly 0), accumulate rowsum and O = e@V.
//   Pass B: recompute QK from registers, write probs = e * (1/rowsum).
// ---------------------------------------------------------------------------

#define SEQ   4096
#define NB    8
#define DIN   256
#define HD    64
#define NROWS (NB * SEQ)                         // 32768
#define PROBS_ELEMS (8LL * 4096LL * 4096LL)

// scratch (allocation-free rule: __device__ globals)
__device__ float g_Q[NROWS * HD];
__device__ float g_K[NROWS * HD];
__device__ float g_V[NROWS * HD];
__device__ float g_keep[NROWS];
__device__ int   g_mask_fmt;

__device__ __forceinline__ uint32_t f2tf(float x) {
    uint32_t y;
    asm("cvt.rna.tf32.f32 %0, %1;" : "=r"(y) : "f"(x));
    return y;
}

__device__ __forceinline__ float fexp2(float x) {
    float y;
    asm("ex2.approx.f32 %0, %1;" : "=f"(y) : "f"(x));
    return y;
}

__device__ __forceinline__ void mma8(float* c, const uint32_t* a, const uint32_t* b) {
    asm volatile(
        "mma.sync.aligned.m16n8k8.row.col.f32.tf32.tf32.f32 "
        "{%0,%1,%2,%3}, {%4,%5,%6,%7}, {%8,%9}, {%0,%1,%2,%3};\n"
        : "+f"(c[0]), "+f"(c[1]), "+f"(c[2]), "+f"(c[3])
        : "r"(a[0]), "r"(a[1]), "r"(a[2]), "r"(a[3]), "r"(b[0]), "r"(b[1]));
}

__device__ __forceinline__ void zero4(float acc[2][4][4]) {
#pragma unroll
    for (int i = 0; i < 2; i++)
#pragma unroll
        for (int j = 0; j < 4; j++)
#pragma unroll
            for (int k = 0; k < 4; k++)
                acc[i][j][k] = 0.0f;
}

// ---------------------------------------------------------------------------
// Mask format detection + decode (bool8 vs int32 vs float32 is ambiguous)
// ---------------------------------------------------------------------------
__global__ void mask_detect_kernel(const uint32_t* __restrict__ mw) {
    __shared__ int iok_s, fok_s;
    if (threadIdx.x == 0) { iok_s = 1; fok_s = 1; }
    __syncthreads();
    int iok = 1, fok = 1;
    // first 8192 words = 32768 bytes: within bounds for every candidate dtype
    for (int i = threadIdx.x; i < NROWS / 4; i += blockDim.x) {
        uint32_t v = mw[i];
        if (v != 0u && v != 1u) iok = 0;
        if (v != 0u && v != 0x3F800000u) fok = 0;
    }
    if (!iok) atomicExch(&iok_s, 0);
    if (!fok) atomicExch(&fok_s, 0);
    __syncthreads();
    if (threadIdx.x == 0) g_mask_fmt = iok_s ? 1 : (fok_s ? 2 : 0);
}

__global__ void mask_decode_kernel(const void* __restrict__ mp) {
    int i = blockIdx.x * blockDim.x + threadIdx.x;
    if (i >= NROWS) return;
    int fmt = g_mask_fmt;
    int masked;
    if (fmt == 1)      masked = ((const int*)mp)[i] != 0;
    else if (fmt == 2) masked = ((const float*)mp)[i] != 0.0f;
    else               masked = ((const unsigned char*)mp)[i] != 0;
    g_keep[i] = masked ? 0.0f : 1.0f;   // mask True = masked out
}

// ---------------------------------------------------------------------------
// Projection kernel (unchanged from R2; small share of runtime).
// blocks [0,256): x -> g_Q ; blocks [256,512): buffer -> g_K, g_V
// 8 warps as 4(M)x2(N), warp tile 32x32.
// ---------------------------------------------------------------------------
#define PROJ_SMEM_FLOATS (128 * 68 + 64 * 68)
#define PROJ_SMEM_BYTES  (PROJ_SMEM_FLOATS * 4)

__device__ __forceinline__ void mma_block_128x64(
    const float* __restrict__ A, const float* __restrict__ Bm,
    float acc[2][4][4], int wm, int wn, int g, int t)
{
#pragma unroll
    for (int ks = 0; ks < 8; ks++) {
        const int k0 = ks * 8;
        uint32_t a[2][4], bb[4][2];
#pragma unroll
        for (int mi = 0; mi < 2; mi++) {
            const float* ap = A + (wm * 32 + mi * 16 + g) * 68 + k0 + t;
            a[mi][0] = f2tf(ap[0]);
            a[mi][1] = f2tf(ap[8 * 68]);
            a[mi][2] = f2tf(ap[4]);
            a[mi][3] = f2tf(ap[8 * 68 + 4]);
        }
#pragma unroll
        for (int ni = 0; ni < 4; ni++) {
            const float* bp = Bm + (wn * 32 + ni * 8 + g) * 68 + k0 + t;
            bb[ni][0] = f2tf(bp[0]);
            bb[ni][1] = f2tf(bp[4]);
        }
#pragma unroll
        for (int mi = 0; mi < 2; mi++)
#pragma unroll
            for (int ni = 0; ni < 4; ni++)
                mma8(acc[mi][ni], a[mi], bb[ni]);
    }
}

__global__ __launch_bounds__(256) void proj_kernel(
    const float* __restrict__ x, const float* __restrict__ buf,
    const float* __restrict__ Wk, const float* __restrict__ bk,
    const float* __restrict__ Wv, const float* __restrict__ bv)
{
    extern __shared__ float sm[];
    float* As = sm;                // 128 x 68
    float* Ws = sm + 128 * 68;     // 64 x 68

    const int tid = threadIdx.x;
    const int lane = tid & 31, wid = tid >> 5;
    const int g = lane >> 2, t = lane & 3;
    const int wm = wid & 3, wn = wid >> 2;
    const bool isx = blockIdx.x < 256;
    const int row0 = (blockIdx.x & 255) * 128;
    const float* in = isx ? x : buf;
    const int nsweep = isx ? 1 : 2;

    for (int sw = 0; sw < nsweep; sw++) {
        const float* W    = (sw == 0) ? Wk : Wv;
        const float* bias = (sw == 0) ? bk : bv;
        float* out = isx ? g_Q : (sw == 0 ? g_K : g_V);

        float acc[2][4][4];
        zero4(acc);

        for (int kc = 0; kc < 4; kc++) {
            __syncthreads();
            for (int i = tid; i < 128 * 16; i += 256) {
                int r = i >> 4, c = (i & 15) * 4;
                float4 v = *(const float4*)&in[(size_t)(row0 + r) * DIN + kc * 64 + c];
                *(float4*)&As[r * 68 + c] = v;
            }
            for (int i = tid; i < 64 * 16; i += 256) {
                int r = i >> 4, c = (i & 15) * 4;
                float4 v = *(const float4*)&W[(size_t)r * DIN + kc * 64 + c];
                *(float4*)&Ws[r * 68 + c] = v;
            }
            __syncthreads();
            mma_block_128x64(As, Ws, acc, wm, wn, g, t);
        }

#pragma unroll
        for (int mi = 0; mi < 2; mi++) {
#pragma unroll
            for (int ni = 0; ni < 4; ni++) {
                int r = row0 + wm * 32 + mi * 16 + g;
                int col = wn * 32 + ni * 8 + t * 2;
                float b0v = __ldg(&bias[col]);
                float b1v = __ldg(&bias[col + 1]);
                out[(size_t)r * HD + col]           = acc[mi][ni][0] + b0v;
                out[(size_t)r * HD + col + 1]       = acc[mi][ni][1] + b1v;
                out[(size_t)(r + 8) * HD + col]     = acc[mi][ni][2] + b0v;
                out[(size_t)(r + 8) * HD + col + 1] = acc[mi][ni][3] + b1v;
            }
        }
    }
}

// ---------------------------------------------------------------------------
// Attention: CTA = 128 threads (4 warps, 2Mx2N, warp tile 32x32),
// q-tile = 64 rows, k-tile = 64 keys. Q fragments in registers.
// SMEM: QE region (Q staging, then E tile), K tile, V tile (all stride 68).
// ---------------------------------------------------------------------------
#define QE_OFF 0
#define AK_OFF (64 * 68)
#define AV_OFF (AK_OFF + 64 * 68)
#define AKP_OFF (AV_OFF + 64 * 68)
#define ARS_OFF (AKP_OFF + 64)
#define AIV_OFF (ARS_OFF + 64)
#define ATTN_SMEM_FLOATS (AIV_OFF + 64)
#define ATTN_SMEM_BYTES  (ATTN_SMEM_FLOATS * 4)

__global__ __launch_bounds__(128, 3) void attn_kernel(float* __restrict__ outp)
{
    extern __shared__ float sm[];
    float* QE     = sm + QE_OFF;    // 64 x 68: Q staging, then E tile (tf32 bits)
    float* Ks     = sm + AK_OFF;    // 64 x 68 (tf32 bits)
    float* Vs     = sm + AV_OFF;    // 64 x 68 (tf32 bits)
    float* kp     = sm + AKP_OFF;   // 64
    float* rowsum = sm + ARS_OFF;   // 64
    float* invs   = sm + AIV_OFF;   // 64

    const int tid = threadIdx.x;
    const int lane = tid & 31, wid = tid >> 5;
    const int g = lane >> 2, t = lane & 3;
    const int wm = wid & 1, wn = wid >> 1;
    const int b = blockIdx.x >> 6;
    const int q0 = (blockIdx.x & 63) * 64;
    const int kbase = b << 12;

    // ---- stage Q (scaled by log2e/8 so e = exp2(mma result)) ----
    const float qscale = 0.125f * 1.4426950408889634f;
    for (int i = tid; i < 64 * 16; i += 128) {
        int r = i >> 4, c = (i & 15) * 4;
        float4 v = *(const float4*)&g_Q[(size_t)(kbase + q0 + r) * HD + c];
        v.x *= qscale; v.y *= qscale; v.z *= qscale; v.w *= qscale;
        *(float4*)&QE[r * 68 + c] = v;
    }
    if (tid < 64) rowsum[tid] = 0.0f;
    __syncthreads();

    // ---- load Q fragments into registers (tf32, persist both passes) ----
    uint32_t aQ[8][2][4];
#pragma unroll
    for (int ks = 0; ks < 8; ks++) {
        const int k0 = ks * 8;
#pragma unroll
        for (int mi = 0; mi < 2; mi++) {
            const float* ap = QE + (wm * 32 + mi * 16 + g) * 68 + k0 + t;
            aQ[ks][mi][0] = f2tf(ap[0]);
            aQ[ks][mi][1] = f2tf(ap[8 * 68]);
            aQ[ks][mi][2] = f2tf(ap[4]);
            aQ[ks][mi][3] = f2tf(ap[8 * 68 + 4]);
        }
    }
    __syncthreads();   // QE region now free for E tiles

    float o[2][4][4];
    zero4(o);

    // ------------------ Pass A: rowsum + O = e @ V ------------------
    for (int kt = 0; kt < 64; kt++) {
        const int kr0 = kbase + kt * 64;
        // stage K and V, pre-converted to tf32 bit patterns
        for (int i = tid; i < 64 * 16; i += 128) {
            int r = i >> 4, c = (i & 15) * 4;
            size_t gi = (size_t)(kr0 + r) * HD + c;
            float4 kv = *(const float4*)&g_K[gi];
            float4 vv = *(const float4*)&g_V[gi];
            uint4 ku = { f2tf(kv.x), f2tf(kv.y), f2tf(kv.z), f2tf(kv.w) };
            uint4 vu = { f2tf(vv.x), f2tf(vv.y), f2tf(vv.z), f2tf(vv.w) };
            *(uint4*)&Ks[r * 68 + c] = ku;
            *(uint4*)&Vs[r * 68 + c] = vu;
        }
        if (tid < 64) kp[tid] = g_keep[kr0 + tid];
        __syncthreads();

        // QK: A from registers, B from SMEM (no cvt)
        float lfr[2][4][4];
        zero4(lfr);
#pragma unroll
        for (int ks = 0; ks < 8; ks++) {
            const int k0 = ks * 8;
            uint32_t bb[4][2];
#pragma unroll
            for (int ni = 0; ni < 4; ni++) {
                const float* bp = Ks + (wn * 32 + ni * 8 + g) * 68 + k0 + t;
                bb[ni][0] = __float_as_uint(bp[0]);
                bb[ni][1] = __float_as_uint(bp[4]);
            }
#pragma unroll
            for (int mi = 0; mi < 2; mi++)
#pragma unroll
                for (int ni = 0; ni < 4; ni++)
                    mma8(lfr[mi][ni], aQ[ks][mi], bb[ni]);
        }

        // epilogue: e = keep * exp2(l); store tf32 bits of e; row sums
        float rsum[2][2] = {{0.f, 0.f}, {0.f, 0.f}};
#pragma unroll
        for (int mi = 0; mi < 2; mi++) {
            const int r = wm * 32 + mi * 16 + g;
#pragma unroll
            for (int ni = 0; ni < 4; ni++) {
                const int col = wn * 32 + ni * 8 + t * 2;
                const float k0v = kp[col], k1v = kp[col + 1];
                float e00 = k0v * fexp2(lfr[mi][ni][0]);
                float e01 = k1v * fexp2(lfr[mi][ni][1]);
                float e10 = k0v * fexp2(lfr[mi][ni][2]);
                float e11 = k1v * fexp2(lfr[mi][ni][3]);
                QE[r * 68 + col]           = __uint_as_float(f2tf(e00));
                QE[r * 68 + col + 1]       = __uint_as_float(f2tf(e01));
                QE[(r + 8) * 68 + col]     = __uint_as_float(f2tf(e10));
                QE[(r + 8) * 68 + col + 1] = __uint_as_float(f2tf(e11));
                rsum[mi][0] += e00 + e01;
                rsum[mi][1] += e10 + e11;
            }
        }
#pragma unroll
        for (int mi = 0; mi < 2; mi++) {
#pragma unroll
            for (int h = 0; h < 2; h++) {
                float v = rsum[mi][h];
                v += __shfl_xor_sync(0xffffffffu, v, 1);
                v += __shfl_xor_sync(0xffffffffu, v, 2);
                if (t == 0) atomicAdd(&rowsum[wm * 32 + mi * 16 + h * 8 + g], v);
            }
        }
        __syncthreads();

        // PV: O += E @ V (both operands pre-converted in SMEM, no cvt)
#pragma unroll
        for (int ks = 0; ks < 8; ks++) {
            const int k0 = ks * 8;
            uint32_t a[2][4], bb[4][2];
#pragma unroll
            for (int mi = 0; mi < 2; mi++) {
                const float* ap = QE + (wm * 32 + mi * 16 + g) * 68 + k0 + t;
                a[mi][0] = __float_as_uint(ap[0]);
                a[mi][1] = __float_as_uint(ap[8 * 68]);
                a[mi][2] = __float_as_uint(ap[4]);
                a[mi][3] = __float_as_uint(ap[8 * 68 + 4]);
            }
#pragma unroll
            for (int ni = 0; ni < 4; ni++) {
                const int n = wn * 32 + ni * 8 + g;
                bb[ni][0] = __float_as_uint(Vs[(k0 + t) * 68 + n]);
                bb[ni][1] = __float_as_uint(Vs[(k0 + t + 4) * 68 + n]);
            }
#pragma unroll
            for (int mi = 0; mi < 2; mi++)
#pragma unroll
                for (int ni = 0; ni < 4; ni++)
                    mma8(o[mi][ni], a[mi], bb[ni]);
        }
        __syncthreads();
    }

    if (tid < 64) invs[tid] = 1.0f / rowsum[tid];
    __syncthreads();

    // ---- write `read` output ----
    {
        float* rout = outp + PROBS_ELEMS;
#pragma unroll
        for (int mi = 0; mi < 2; mi++) {
            const int r = wm * 32 + mi * 16 + g;
            const float i0 = invs[r], i1 = invs[r + 8];
#pragma unroll
            for (int ni = 0; ni < 4; ni++) {
                const int col = wn * 32 + ni * 8 + t * 2;
                size_t o0 = (size_t)(kbase + q0 + r) * HD + col;
                size_t o1 = (size_t)(kbase + q0 + r + 8) * HD + col;
                rout[o0]     = o[mi][ni][0] * i0;
                rout[o0 + 1] = o[mi][ni][1] * i0;
                rout[o1]     = o[mi][ni][2] * i1;
                rout[o1 + 1] = o[mi][ni][3] * i1;
            }
        }
    }

    // ------------------ Pass B: recompute QK, write probs -----------
    for (int kt = 0; kt < 64; kt++) {
        const int kr0 = kbase + kt * 64;
        __syncthreads();
        for (int i = tid; i < 64 * 16; i += 128) {
            int r = i >> 4, c = (i & 15) * 4;
            float4 kv = *(const float4*)&g_K[(size_t)(kr0 + r) * HD + c];
            uint4 ku = { f2tf(kv.x), f2tf(kv.y), f2tf(kv.z), f2tf(kv.w) };
            *(uint4*)&Ks[r * 68 + c] = ku;
        }
        if (tid < 64) kp[tid] = g_keep[kr0 + tid];
        __syncthreads();

        float lfr[2][4][4];
        zero4(lfr);
#pragma unroll
        for (int ks = 0; ks < 8; ks++) {
            const int k0 = ks * 8;
            uint32_t bb[4][2];
#pragma unroll
            for (int ni = 0; ni < 4; ni++) {
                const float* bp = Ks + (wn * 32 + ni * 8 + g) * 68 + k0 + t;
                bb[ni][0] = __float_as_uint(bp[0]);
                bb[ni][1] = __float_as_uint(bp[4]);
            }
#pragma unroll
            for (int mi = 0; mi < 2; mi++)
#pragma unroll
                for (int ni = 0; ni < 4; ni++)
                    mma8(lfr[mi][ni], aQ[ks][mi], bb[ni]);
        }

#pragma unroll
        for (int mi = 0; mi < 2; mi++) {
            const int r = wm * 32 + mi * 16 + g;
            const float i0 = invs[r], i1 = invs[r + 8];
#pragma unroll
            for (int ni = 0; ni < 4; ni++) {
                const int col = wn * 32 + ni * 8 + t * 2;
                const float k0v = kp[col] * i0, k1v = kp[col + 1] * i0;
                const float k2v = kp[col] * i1, k3v = kp[col + 1] * i1;
                float2 p0, p1;
                p0.x = k0v * fexp2(lfr[mi][ni][0]);
                p0.y = k1v * fexp2(lfr[mi][ni][1]);
                p1.x = k2v * fexp2(lfr[mi][ni][2]);
                p1.y = k3v * fexp2(lfr[mi][ni][3]);
                size_t base0 = ((size_t)(kbase + q0 + r)) * SEQ + kt * 64 + col;
                size_t base1 = ((size_t)(kbase + q0 + r + 8)) * SEQ + kt * 64 + col;
                *(float2*)&outp[base0] = p0;
                *(float2*)&outp[base1] = p1;
            }
        }
    }
}

// ---------------------------------------------------------------------------
extern "C" void kernel_launch(void* const* d_in, const int* in_sizes, int n_in,
                              void* d_out, int out_size) {
    const float* x   = (const float*)d_in[0];
    const float* buf = (const float*)d_in[1];
    const void*  msk = d_in[2];
    const float* Wk  = (const float*)d_in[3];
    const float* bk  = (const float*)d_in[4];
    const float* Wv  = (const float*)d_in[5];
    const float* bv  = (const float*)d_in[6];
    float* outp = (float*)d_out;

    cudaFuncSetAttribute(proj_kernel, cudaFuncAttributeMaxDynamicSharedMemorySize,
                         PROJ_SMEM_BYTES);
    cudaFuncSetAttribute(attn_kernel, cudaFuncAttributeMaxDynamicSharedMemorySize,
                         ATTN_SMEM_BYTES);

    proj_kernel<<<512, 256, PROJ_SMEM_BYTES>>>(x, buf, Wk, bk, Wv, bv);
    mask_detect_kernel<<<1, 256>>>((const uint32_t*)msk);
    mask_decode_kernel<<<NROWS / 256, 256>>>(msk);
    attn_kernel<<<512, 128, ATTN_SMEM_BYTES>>>(outp);
}

// round 7
// speedup vs baseline: 1.3301x; 1.3301x over previous
#include <cuda_runtime.h>
#include <cstdint>
#include <cstddef>

// ---------------------------------------------------------------------------
// BufferAttend1d (sm_100, legacy mma.sync tf32 — tcgen05 unavailable at
// compute_100 virtual arch). B=8, Q=K=4096, DIN=256, d=64.
// Output: probs (8*4096*4096 f32) ++ read (8*4096*64 f32).
//
// proj: x->Q (pre-scaled by log2e/8, tf32 bits), buffer->K,V (tf32 bits).
// attn (one pass): per q-tile(64) loop k-tiles(64) with cp.async double
//   buffering: QK mma -> e = keep*exp2(l) -> E smem (tf32) -> PV mma and
//   coalesced unnormalized-e store to probs region; register rowsum -> g_inv.
// rescale: probs *= inv[row]  (pure streaming, separate kernel).
// ---------------------------------------------------------------------------

#define SEQ   4096
#define NB    8
#define DIN   256
#define HD    64
#define NROWS (NB*SEQ)
#define PROBS_ELEMS (8LL*4096LL*4096LL)
#define KT2   64
#define NT2   (SEQ/KT2)    // 64

// attn smem byte offsets (row stride 272B = 68 floats)
#define QE_B  0
#define K_B   17408
#define V_B   (17408*3)
#define KP_B  (17408*5)
#define RS_B  (17408*5 + 512)
#define IV_B  (RS_B + 512)
#define ATTN_SMEM (IV_B + 256)

__device__ float g_Q[NROWS*HD];
__device__ float g_K[NROWS*HD];
__device__ float g_V[NROWS*HD];
__device__ float g_keep[NROWS];
__device__ float g_inv[NROWS];
__device__ int   g_mask_fmt;

__device__ __forceinline__ uint32_t f2tf(float x){uint32_t y;asm("cvt.rna.tf32.f32 %0, %1;":"=r"(y):"f"(x));return y;}
__device__ __forceinline__ float fexp2(float x){float y;asm("ex2.approx.f32 %0, %1;":"=f"(y):"f"(x));return y;}
__device__ __forceinline__ uint32_t smem_u32(const void* p){uint32_t a;asm("{ .reg .u64 t; cvta.to.shared.u64 t, %1; cvt.u32.u64 %0, t; }":"=r"(a):"l"(p));return a;}
__device__ __forceinline__ void cpa16(uint32_t s, const void* g){
    asm volatile("cp.async.cg.shared.global [%0], [%1], 16;"::"r"(s),"l"(g));
}
#define CP_COMMIT() asm volatile("cp.async.commit_group;" ::: "memory")
#define CP_WAIT1()  asm volatile("cp.async.wait_group 1;" ::: "memory")
#define CP_WAIT0()  asm volatile("cp.async.wait_group 0;" ::: "memory")

__device__ __forceinline__ void mma8(float* c, const uint32_t* a, const uint32_t* b){
    asm volatile("mma.sync.aligned.m16n8k8.row.col.f32.tf32.tf32.f32 "
        "{%0,%1,%2,%3}, {%4,%5,%6,%7}, {%8,%9}, {%0,%1,%2,%3};\n"
        : "+f"(c[0]),"+f"(c[1]),"+f"(c[2]),"+f"(c[3])
        : "r"(a[0]),"r"(a[1]),"r"(a[2]),"r"(a[3]),"r"(b[0]),"r"(b[1]));
}
__device__ __forceinline__ void zero4(float a[2][4][4]){
#pragma unroll
    for(int i=0;i<2;i++)
#pragma unroll
        for(int j=0;j<4;j++)
#pragma unroll
            for(int k=0;k<4;k++) a[i][j][k]=0.f;
}

// ---------------- mask ----------------
__global__ void mask_detect_kernel(const uint32_t* __restrict__ mw){
    __shared__ int iok_s, fok_s;
    if(threadIdx.x==0){iok_s=1;fok_s=1;}
    __syncthreads();
    int iok=1, fok=1;
    for(int i=threadIdx.x;i<NROWS/4;i+=blockDim.x){
        uint32_t v=mw[i];
        if(v!=0u&&v!=1u) iok=0;
        if(v!=0u&&v!=0x3F800000u) fok=0;
    }
    if(!iok) atomicExch(&iok_s,0);
    if(!fok) atomicExch(&fok_s,0);
    __syncthreads();
    if(threadIdx.x==0) g_mask_fmt = iok_s?1:(fok_s?2:0);
}
__global__ void mask_decode_kernel(const void* __restrict__ mp){
    int i=blockIdx.x*blockDim.x+threadIdx.x;
    if(i>=NROWS) return;
    int f=g_mask_fmt, m;
    if(f==1) m=((const int*)mp)[i]!=0;
    else if(f==2) m=((const float*)mp)[i]!=0.0f;
    else m=((const unsigned char*)mp)[i]!=0;
    g_keep[i]= m?0.0f:1.0f;
}

// ---------------- projection: outputs tf32 bit patterns ----------------
#define PROJ_SMEM_BYTES ((128*68+64*68)*4)
__global__ __launch_bounds__(256) void proj_kernel(
    const float* __restrict__ x, const float* __restrict__ buf,
    const float* __restrict__ Wk, const float* __restrict__ bk,
    const float* __restrict__ Wv, const float* __restrict__ bv)
{
    extern __shared__ float sm[];
    float* As=sm; float* Ws=sm+128*68;
    const int tid=threadIdx.x, lane=tid&31, wid=tid>>5;
    const int g=lane>>2, t=lane&3, wm=wid&3, wn=wid>>2;
    const bool isx = blockIdx.x<256;
    const int row0=(blockIdx.x&255)*128;
    const float* in = isx?x:buf;
    const int nsweep = isx?1:2;
    const float osc = isx ? 0.125f*1.4426950408889634f : 1.0f;

    for(int sw=0; sw<nsweep; sw++){
        const float* W=(sw==0)?Wk:Wv;
        const float* bias=(sw==0)?bk:bv;
        float* out = isx?g_Q:(sw==0?g_K:g_V);
        float acc[2][4][4];
        zero4(acc);
        for(int kc=0;kc<4;kc++){
            __syncthreads();
            for(int i=tid;i<128*16;i+=256){
                int r=i>>4,c=(i&15)*4;
                *(float4*)&As[r*68+c] = *(const float4*)&in[(size_t)(row0+r)*DIN+kc*64+c];
            }
            for(int i=tid;i<64*16;i+=256){
                int r=i>>4,c=(i&15)*4;
                *(float4*)&Ws[r*68+c] = *(const float4*)&W[(size_t)r*DIN+kc*64+c];
            }
            __syncthreads();
#pragma unroll
            for(int ks=0;ks<8;ks++){
                const int k0=ks*8;
                uint32_t a[2][4], bb[4][2];
#pragma unroll
                for(int mi=0;mi<2;mi++){
                    const float* ap=As+(wm*32+mi*16+g)*68+k0+t;
                    a[mi][0]=f2tf(ap[0]); a[mi][1]=f2tf(ap[8*68]);
                    a[mi][2]=f2tf(ap[4]); a[mi][3]=f2tf(ap[8*68+4]);
                }
#pragma unroll
                for(int ni=0;ni<4;ni++){
                    const float* bp=Ws+(wn*32+ni*8+g)*68+k0+t;
                    bb[ni][0]=f2tf(bp[0]); bb[ni][1]=f2tf(bp[4]);
                }
#pragma unroll
                for(int mi=0;mi<2;mi++)
#pragma unroll
                    for(int ni=0;ni<4;ni++) mma8(acc[mi][ni],a[mi],bb[ni]);
            }
        }
#pragma unroll
        for(int mi=0;mi<2;mi++)
#pragma unroll
            for(int ni=0;ni<4;ni++){
                int r=row0+wm*32+mi*16+g, col=wn*32+ni*8+t*2;
                float b0=__ldg(&bias[col]), b1=__ldg(&bias[col+1]);
                out[(size_t)r*HD+col]      =__uint_as_float(f2tf((acc[mi][ni][0]+b0)*osc));
                out[(size_t)r*HD+col+1]    =__uint_as_float(f2tf((acc[mi][ni][1]+b1)*osc));
                out[(size_t)(r+8)*HD+col]  =__uint_as_float(f2tf((acc[mi][ni][2]+b0)*osc));
                out[(size_t)(r+8)*HD+col+1]=__uint_as_float(f2tf((acc[mi][ni][3]+b1)*osc));
            }
    }
}

// ---------------- attention (single pass, cp.async pipelined) ----------------
__device__ __forceinline__ void stage_cp(uint32_t sb, int bi, int kr, int tid){
    const uint32_t kd = sb + K_B + bi*17408;
    const uint32_t vd = sb + V_B + bi*17408;
    const char* kg = (const char*)(g_K + (size_t)kr*HD);
    const char* vg = (const char*)(g_V + (size_t)kr*HD);
#pragma unroll
    for(int j=0;j<8;j++){
        int idx = tid + j*128;          // 0..1023 float4 chunks
        uint32_t off = (uint32_t)(idx>>4)*272 + (uint32_t)(idx&15)*16;
        cpa16(kd+off, kg + (size_t)idx*16);
        cpa16(vd+off, vg + (size_t)idx*16);
    }
    if(tid<16) cpa16(sb+KP_B+bi*256+tid*16, (const char*)(g_keep+kr)+tid*16);
}

__global__ __launch_bounds__(128) void attn_kernel(float* __restrict__ outp)
{
    extern __shared__ char smc[];
    const uint32_t sb = smem_u32(smc);
    float* QE  =(float*)(smc+QE_B);
    float* rs2 =(float*)(smc+RS_B);
    float* invs=(float*)(smc+IV_B);

    const int tid=threadIdx.x, lane=tid&31, wid=tid>>5;
    const int g=lane>>2, t=lane&3;
    const int wm=wid&1, wn=wid>>1;
    const int b=blockIdx.x>>6, q0=(blockIdx.x&63)*64;
    const int kb0=b<<12;

    // stage Q (tf32 bits, pre-scaled by proj) into QE
    for(int idx=tid; idx<1024; idx+=128){
        int r=idx>>4, c=(idx&15)*4;
        *(float4*)(smc+QE_B+(size_t)r*272+(size_t)c*4) =
            *(const float4*)&g_Q[(size_t)(kb0+q0+r)*HD+c];
    }
    __syncthreads();
    uint32_t aQ[8][2][4];
#pragma unroll
    for(int ks=0;ks<8;ks++){
        const int k0=ks*8;
#pragma unroll
        for(int mi=0;mi<2;mi++){
            const float* ap=QE+(wm*32+mi*16+g)*68+k0+t;
            aQ[ks][mi][0]=__float_as_uint(ap[0]);
            aQ[ks][mi][1]=__float_as_uint(ap[8*68]);
            aQ[ks][mi][2]=__float_as_uint(ap[4]);
            aQ[ks][mi][3]=__float_as_uint(ap[8*68+4]);
        }
    }
    __syncthreads();   // QE now free for E tiles

    // prologue: stage tile 0
    stage_cp(sb, 0, kb0, tid);
    CP_COMMIT();

    float o[2][4][4];
    zero4(o);
    float rsum[2][2]={{0.f,0.f},{0.f,0.f}};

    for(int i=0;i<NT2;i++){
        const int cur=i&1;
        __syncthreads();   // prior compute done: safe to overwrite buf(cur^1) and E
        if(i+1<NT2){
            stage_cp(sb, cur^1, kb0+(i+1)*KT2, tid);
            CP_COMMIT();
            CP_WAIT1();
        } else {
            CP_WAIT0();
        }
        __syncthreads();   // buf(cur) visible to all

        // ---- QK: lfr = Q @ K^T (A in regs, B in smem; tf32 bits throughout)
        const float* Ksm=(const float*)(smc+K_B+cur*17408);
        float lfr[2][4][4];
        zero4(lfr);
#pragma unroll
        for(int ks=0;ks<8;ks++){
            const int k0=ks*8;
            uint32_t bb[4][2];
#pragma unroll
            for(int ni=0;ni<4;ni++){
                const float* bp=Ksm+(wn*32+ni*8+g)*68+k0+t;
                bb[ni][0]=__float_as_uint(bp[0]);
                bb[ni][1]=__float_as_uint(bp[4]);
            }
#pragma unroll
            for(int mi=0;mi<2;mi++)
#pragma unroll
                for(int ni=0;ni<4;ni++) mma8(lfr[mi][ni],aQ[ks][mi],bb[ni]);
        }

        // ---- epilogue: e = keep * exp2(l); E (tf32 bits) -> smem; reg rowsum
        const float* kp=(const float*)(smc+KP_B+cur*256);
#pragma unroll
        for(int mi=0;mi<2;mi++){
            const int r=wm*32+mi*16+g;
#pragma unroll
            for(int ni=0;ni<4;ni++){
                const int col=wn*32+ni*8+t*2;
                const float k0v=kp[col], k1v=kp[col+1];
                float e00=k0v*fexp2(lfr[mi][ni][0]);
                float e01=k1v*fexp2(lfr[mi][ni][1]);
                float e10=k0v*fexp2(lfr[mi][ni][2]);
                float e11=k1v*fexp2(lfr[mi][ni][3]);
                QE[r*68+col]      =__uint_as_float(f2tf(e00));
                QE[r*68+col+1]    =__uint_as_float(f2tf(e01));
                QE[(r+8)*68+col]  =__uint_as_float(f2tf(e10));
                QE[(r+8)*68+col+1]=__uint_as_float(f2tf(e11));
                rsum[mi][0]+=e00+e01;
                rsum[mi][1]+=e10+e11;
            }
        }
        __syncthreads();   // E visible

        // ---- PV: O += E @ V
        const float* Vsm=(const float*)(smc+V_B+cur*17408);
#pragma unroll
        for(int ks=0;ks<8;ks++){
            const int k0=ks*8;
            uint32_t a[2][4], bb[4][2];
#pragma unroll
            for(int mi=0;mi<2;mi++){
                const float* ap=QE+(wm*32+mi*16+g)*68+k0+t;
                a[mi][0]=__float_as_uint(ap[0]);
                a[mi][1]=__float_as_uint(ap[8*68]);
                a[mi][2]=__float_as_uint(ap[4]);
                a[mi][3]=__float_as_uint(ap[8*68+4]);
            }
#pragma unroll
            for(int ni=0;ni<4;ni++){
                const int n=wn*32+ni*8+g;
                bb[ni][0]=__float_as_uint(Vsm[(k0+t)*68+n]);
                bb[ni][1]=__float_as_uint(Vsm[(k0+t+4)*68+n]);
            }
#pragma unroll
            for(int mi=0;mi<2;mi++)
#pragma unroll
                for(int ni=0;ni<4;ni++) mma8(o[mi][ni],a[mi],bb[ni]);
        }

        // ---- coalesced e store: warp wid copies rows [wid*16, wid*16+16)
        {
            const int rb = wid*16 + (lane>>4);     // 2 rows per iteration
            const int c  = (lane&15)*4;
#pragma unroll
            for(int j=0;j<8;j++){
                const int r = rb + j*2;
                float4 v = *(const float4*)(smc+QE_B+(size_t)r*272+(size_t)c*4);
                *(float4*)&outp[(size_t)(kb0+q0+r)*SEQ + (size_t)i*KT2 + c] = v;
            }
        }
    }

    // ---- deterministic rowsum reduce -> inv
#pragma unroll
    for(int mi=0;mi<2;mi++)
#pragma unroll
        for(int h=0;h<2;h++){
            float v=rsum[mi][h];
            v+=__shfl_xor_sync(0xffffffffu,v,1);
            v+=__shfl_xor_sync(0xffffffffu,v,2);
            if(t==0) rs2[(wm*32+mi*16+h*8+g)*2+wn]=v;
        }
    __syncthreads();
    if(tid<64){
        float inv=1.0f/(rs2[2*tid]+rs2[2*tid+1]);
        invs[tid]=inv;
        g_inv[kb0+q0+tid]=inv;
    }
    __syncthreads();

    // ---- read output
    {
        float* rout = outp + PROBS_ELEMS;
#pragma unroll
        for(int mi=0;mi<2;mi++){
            const int r=wm*32+mi*16+g;
            const float i0=invs[r], i1=invs[r+8];
#pragma unroll
            for(int ni=0;ni<4;ni++){
                const int col=wn*32+ni*8+t*2;
                size_t o0=(size_t)(kb0+q0+r)*HD+col;
                size_t o1=(size_t)(kb0+q0+r+8)*HD+col;
                rout[o0]  =o[mi][ni][0]*i0;
                rout[o0+1]=o[mi][ni][1]*i0;
                rout[o1]  =o[mi][ni][2]*i1;
                rout[o1+1]=o[mi][ni][3]*i1;
            }
        }
    }
}

// ---------------- rescale: probs *= inv[row] (streaming) ----------------
__global__ __launch_bounds__(256) void rescale_kernel(float* __restrict__ p)
{
    const int row = blockIdx.x;
    const float inv = __ldg(&g_inv[row]);
    float4* pr = (float4*)(p + (size_t)row*SEQ);
    const int t = threadIdx.x;
#pragma unroll
    for(int j=0;j<4;j++){
        float4 v = pr[t + j*256];
        v.x*=inv; v.y*=inv; v.z*=inv; v.w*=inv;
        pr[t + j*256] = v;
    }
}

// ---------------------------------------------------------------------------
extern "C" void kernel_launch(void* const* d_in, const int* in_sizes, int n_in,
                              void* d_out, int out_size) {
    const float* x  =(const float*)d_in[0];
    const float* buf=(const float*)d_in[1];
    const void*  msk=d_in[2];
    const float* Wk =(const float*)d_in[3];
    const float* bk =(const float*)d_in[4];
    const float* Wv =(const float*)d_in[5];
    const float* bv =(const float*)d_in[6];
    float* outp=(float*)d_out;

    cudaFuncSetAttribute(proj_kernel, cudaFuncAttributeMaxDynamicSharedMemorySize, PROJ_SMEM_BYTES);
    cudaFuncSetAttribute(attn_kernel, cudaFuncAttributeMaxDynamicSharedMemorySize, ATTN_SMEM);

    proj_kernel<<<512, 256, PROJ_SMEM_BYTES>>>(x, buf, Wk, bk, Wv, bv);
    mask_detect_kernel<<<1, 256>>>((const uint32_t*)msk);
    mask_decode_kernel<<<NROWS/256, 256>>>(msk);
    attn_kernel<<<512, 128, ATTN_SMEM>>>(outp);
    rescale_kernel<<<NROWS, 256>>>(outp);
}

// round 8
// speedup vs baseline: 1.5458x; 1.1622x over previous
#include <cuda_runtime.h>
#include <cuda_fp16.h>
#include <cstdint>
#include <cstddef>

// ---------------------------------------------------------------------------
// BufferAttend1d (sm_100 legacy mma path). B=8, Q=K=4096, DIN=256, d=64.
// Output: probs (8*4096*4096 f32) ++ read (8*4096*64 f32).
//
// proj: x->g_Q (tf32 bits, pre-scaled log2e/8), buffer->g_K (tf32 bits),
//       buffer->g_Vt (fp16, TRANSPOSED [b*64+vd][seq]).
// attn: q-tile 64, k-tile 64, cp.async double buffered.
//   QK  tf32 mma (Q regs, K smem) -> e = keep*exp2(l) -> E fp16 smem
//   PV  fp16 m16n8k16 (E smem, Vt smem) accumulates O in f32 regs
//   probs <- E tile (fp16->f32, coalesced); rowsum in regs -> inv (smem)
//   tail: CTA rescales its own 64 probs rows by inv (overlapped across CTAs).
// ---------------------------------------------------------------------------

#define SEQ   4096
#define NB    8
#define DIN   256
#define HD    64
#define NROWS (NB*SEQ)
#define PROBS_ELEMS (8LL*4096LL*4096LL)
#define KT2   64
#define NT2   (SEQ/KT2)    // 64

// attn smem byte offsets
#define E_B   0              // 64 rows x 144B (72 halves)          = 9216
#define K_B   9216           // 2 x (64 rows x 272B)                = 34816
#define V_B   44032          // 2 x (64 vd-rows x 144B fp16)        = 18432
#define KP_B  62464          // 2 x 256
#define RS_B  62976          // 512
#define IV_B  63488          // 256
#define ATTN_SMEM 63744

__device__ float    g_Q[NROWS*HD];
__device__ float    g_K[NROWS*HD];
__device__ uint16_t g_Vt[(size_t)NB*HD*SEQ];   // [b*64+vd][seq] fp16
__device__ float    g_keep[NROWS];
__device__ int      g_mask_fmt;

__device__ __forceinline__ uint32_t f2tf(float x){uint32_t y;asm("cvt.rna.tf32.f32 %0, %1;":"=r"(y):"f"(x));return y;}
__device__ __forceinline__ uint16_t f2h(float x){uint16_t u;asm("cvt.rn.f16.f32 %0, %1;":"=h"(u):"f"(x));return u;}
__device__ __forceinline__ float fexp2(float x){float y;asm("ex2.approx.f32 %0, %1;":"=f"(y):"f"(x));return y;}
__device__ __forceinline__ uint32_t smem_u32(const void* p){uint32_t a;asm("{ .reg .u64 t; cvta.to.shared.u64 t, %1; cvt.u32.u64 %0, t; }":"=r"(a):"l"(p));return a;}
__device__ __forceinline__ void cpa16(uint32_t s, const void* g){
    asm volatile("cp.async.cg.shared.global [%0], [%1], 16;"::"r"(s),"l"(g));
}
#define CP_COMMIT() asm volatile("cp.async.commit_group;" ::: "memory")
#define CP_WAIT1()  asm volatile("cp.async.wait_group 1;" ::: "memory")
#define CP_WAIT0()  asm volatile("cp.async.wait_group 0;" ::: "memory")

__device__ __forceinline__ void mma8(float* c, const uint32_t* a, const uint32_t* b){
    asm volatile("mma.sync.aligned.m16n8k8.row.col.f32.tf32.tf32.f32 "
        "{%0,%1,%2,%3}, {%4,%5,%6,%7}, {%8,%9}, {%0,%1,%2,%3};\n"
        : "+f"(c[0]),"+f"(c[1]),"+f"(c[2]),"+f"(c[3])
        : "r"(a[0]),"r"(a[1]),"r"(a[2]),"r"(a[3]),"r"(b[0]),"r"(b[1]));
}
__device__ __forceinline__ void mma16h(float* c, const uint32_t* a, const uint32_t* b){
    asm volatile("mma.sync.aligned.m16n8k16.row.col.f32.f16.f16.f32 "
        "{%0,%1,%2,%3}, {%4,%5,%6,%7}, {%8,%9}, {%0,%1,%2,%3};\n"
        : "+f"(c[0]),"+f"(c[1]),"+f"(c[2]),"+f"(c[3])
        : "r"(a[0]),"r"(a[1]),"r"(a[2]),"r"(a[3]),"r"(b[0]),"r"(b[1]));
}
__device__ __forceinline__ void zero4(float a[2][4][4]){
#pragma unroll
    for(int i=0;i<2;i++)
#pragma unroll
        for(int j=0;j<4;j++)
#pragma unroll
            for(int k=0;k<4;k++) a[i][j][k]=0.f;
}

// ---------------- mask ----------------
__global__ void mask_detect_kernel(const uint32_t* __restrict__ mw){
    __shared__ int iok_s, fok_s;
    if(threadIdx.x==0){iok_s=1;fok_s=1;}
    __syncthreads();
    int iok=1, fok=1;
    for(int i=threadIdx.x;i<NROWS/4;i+=blockDim.x){
        uint32_t v=mw[i];
        if(v!=0u&&v!=1u) iok=0;
        if(v!=0u&&v!=0x3F800000u) fok=0;
    }
    if(!iok) atomicExch(&iok_s,0);
    if(!fok) atomicExch(&fok_s,0);
    __syncthreads();
    if(threadIdx.x==0) g_mask_fmt = iok_s?1:(fok_s?2:0);
}
__global__ void mask_decode_kernel(const void* __restrict__ mp){
    int i=blockIdx.x*blockDim.x+threadIdx.x;
    if(i>=NROWS) return;
    int f=g_mask_fmt, m;
    if(f==1) m=((const int*)mp)[i]!=0;
    else if(f==2) m=((const float*)mp)[i]!=0.0f;
    else m=((const unsigned char*)mp)[i]!=0;
    g_keep[i]= m?0.0f:1.0f;
}

// ---------------- projection ----------------
#define PROJ_SMEM_BYTES ((128*68+64*68)*4)
__global__ __launch_bounds__(256) void proj_kernel(
    const float* __restrict__ x, const float* __restrict__ buf,
    const float* __restrict__ Wk, const float* __restrict__ bk,
    const float* __restrict__ Wv, const float* __restrict__ bv)
{
    extern __shared__ float sm[];
    float* As=sm; float* Ws=sm+128*68;
    const int tid=threadIdx.x, lane=tid&31, wid=tid>>5;
    const int g=lane>>2, t=lane&3, wm=wid&3, wn=wid>>2;
    const bool isx = blockIdx.x<256;
    const int row0=(blockIdx.x&255)*128;
    const float* in = isx?x:buf;
    const int nsweep = isx?1:2;
    const float osc = isx ? 0.125f*1.4426950408889634f : 1.0f;

    for(int sw=0; sw<nsweep; sw++){
        const float* W=(sw==0)?Wk:Wv;
        const float* bias=(sw==0)?bk:bv;
        const int isV = (!isx) && (sw==1);
        float* out = isx?g_Q:g_K;
        float acc[2][4][4];
        zero4(acc);
        for(int kc=0;kc<4;kc++){
            __syncthreads();
            for(int i=tid;i<128*16;i+=256){
                int r=i>>4,c=(i&15)*4;
                *(float4*)&As[r*68+c] = *(const float4*)&in[(size_t)(row0+r)*DIN+kc*64+c];
            }
            for(int i=tid;i<64*16;i+=256){
                int r=i>>4,c=(i&15)*4;
                *(float4*)&Ws[r*68+c] = *(const float4*)&W[(size_t)r*DIN+kc*64+c];
            }
            __syncthreads();
#pragma unroll
            for(int ks=0;ks<8;ks++){
                const int k0=ks*8;
                uint32_t a[2][4], bb[4][2];
#pragma unroll
                for(int mi=0;mi<2;mi++){
                    const float* ap=As+(wm*32+mi*16+g)*68+k0+t;
                    a[mi][0]=f2tf(ap[0]); a[mi][1]=f2tf(ap[8*68]);
                    a[mi][2]=f2tf(ap[4]); a[mi][3]=f2tf(ap[8*68+4]);
                }
#pragma unroll
                for(int ni=0;ni<4;ni++){
                    const float* bp=Ws+(wn*32+ni*8+g)*68+k0+t;
                    bb[ni][0]=f2tf(bp[0]); bb[ni][1]=f2tf(bp[4]);
                }
#pragma unroll
                for(int mi=0;mi<2;mi++)
#pragma unroll
                    for(int ni=0;ni<4;ni++) mma8(acc[mi][ni],a[mi],bb[ni]);
            }
        }
#pragma unroll
        for(int mi=0;mi<2;mi++)
#pragma unroll
            for(int ni=0;ni<4;ni++){
                int r=row0+wm*32+mi*16+g, col=wn*32+ni*8+t*2;
                float b0=__ldg(&bias[col]), b1=__ldg(&bias[col+1]);
                float v00=acc[mi][ni][0]+b0, v01=acc[mi][ni][1]+b1;
                float v10=acc[mi][ni][2]+b0, v11=acc[mi][ni][3]+b1;
                if(isV){
                    // transposed fp16: g_Vt[(b*64+col)<<12 | seq]
                    int b_  = r>>12,      s0 = r&4095;
                    int b2  = (r+8)>>12,  s1 = (r+8)&4095;
                    g_Vt[((size_t)(b_*64+col  )<<12)+s0]=f2h(v00);
                    g_Vt[((size_t)(b_*64+col+1)<<12)+s0]=f2h(v01);
                    g_Vt[((size_t)(b2*64+col  )<<12)+s1]=f2h(v10);
                    g_Vt[((size_t)(b2*64+col+1)<<12)+s1]=f2h(v11);
                } else {
                    out[(size_t)r*HD+col]      =__uint_as_float(f2tf(v00*osc));
                    out[(size_t)r*HD+col+1]    =__uint_as_float(f2tf(v01*osc));
                    out[(size_t)(r+8)*HD+col]  =__uint_as_float(f2tf(v10*osc));
                    out[(size_t)(r+8)*HD+col+1]=__uint_as_float(f2tf(v11*osc));
                }
            }
    }
}

// ---------------- attention ----------------
__device__ __forceinline__ void stage_cp(uint32_t sb, int bi, int krg, int b, int k0l, int tid){
    // K tile: 64 rows x 64 f32, smem stride 272B
    const uint32_t kd = sb + K_B + bi*17408;
    const char* kg = (const char*)(g_K + (size_t)krg*HD);
#pragma unroll
    for(int j=0;j<8;j++){
        int idx = tid + j*128;
        uint32_t off = (uint32_t)(idx>>4)*272 + (uint32_t)(idx&15)*16;
        cpa16(kd+off, kg + (size_t)idx*16);
    }
    // Vt tile: 64 vd-rows x 64 keys fp16 (128B/row), smem stride 144B
    const uint32_t vd = sb + V_B + bi*9216;
#pragma unroll
    for(int j=0;j<4;j++){
        int idx = tid + j*128;             // 0..511
        int row = idx>>3, ch = idx&7;
        cpa16(vd + (uint32_t)row*144 + (uint32_t)ch*16,
              (const char*)(g_Vt + ((size_t)(b*64+row)<<12) + k0l + ch*8));
    }
    if(tid<16) cpa16(sb+KP_B+bi*256+tid*16, (const char*)(g_keep+krg)+tid*16);
}

__global__ __launch_bounds__(128,3) void attn_kernel(float* __restrict__ outp)
{
    extern __shared__ char smc[];
    const uint32_t sb = smem_u32(smc);
    float* rs2 =(float*)(smc+RS_B);
    float* invs=(float*)(smc+IV_B);

    const int tid=threadIdx.x, lane=tid&31, wid=tid>>5;
    const int g=lane>>2, t=lane&3;
    const int wm=wid&1, wn=wid>>1;
    const int b=blockIdx.x>>6, q0=(blockIdx.x&63)*64;
    const int kb0=b<<12;

    // stage Q (tf32 bits) into K buffer 0 temporarily, load aQ regs
    for(int idx=tid; idx<1024; idx+=128){
        int r=idx>>4, c=(idx&15)*4;
        *(float4*)(smc+K_B+(size_t)r*272+(size_t)c*4) =
            *(const float4*)&g_Q[(size_t)(kb0+q0+r)*HD+c];
    }
    __syncthreads();
    uint32_t aQ[8][2][4];
    {
        const float* Qs=(const float*)(smc+K_B);
#pragma unroll
        for(int ks=0;ks<8;ks++){
            const int k0=ks*8;
#pragma unroll
            for(int mi=0;mi<2;mi++){
                const float* ap=Qs+(wm*32+mi*16+g)*68+k0+t;
                aQ[ks][mi][0]=__float_as_uint(ap[0]);
                aQ[ks][mi][1]=__float_as_uint(ap[8*68]);
                aQ[ks][mi][2]=__float_as_uint(ap[4]);
                aQ[ks][mi][3]=__float_as_uint(ap[8*68+4]);
            }
        }
    }
    __syncthreads();

    // prologue: stage tile 0
    stage_cp(sb, 0, kb0, b, 0, tid);
    CP_COMMIT();

    float o[2][4][4];
    zero4(o);
    float rsum[2][2]={{0.f,0.f},{0.f,0.f}};

    for(int i=0;i<NT2;i++){
        const int cur=i&1;
        __syncthreads();                       // prior readers of buf(cur^1), E done
        if(i+1<NT2){
            stage_cp(sb, cur^1, kb0+(i+1)*KT2, b, (i+1)*KT2, tid);
            CP_COMMIT();
            CP_WAIT1();
        } else {
            CP_WAIT0();
        }
        __syncthreads();                       // buf(cur) visible

        // ---- QK (tf32): lfr = Q @ K^T
        const float* Ksm=(const float*)(smc+K_B+cur*17408);
        float lfr[2][4][4];
        zero4(lfr);
#pragma unroll
        for(int ks=0;ks<8;ks++){
            const int k0=ks*8;
            uint32_t bb[4][2];
#pragma unroll
            for(int ni=0;ni<4;ni++){
                const float* bp=Ksm+(wn*32+ni*8+g)*68+k0+t;
                bb[ni][0]=__float_as_uint(bp[0]);
                bb[ni][1]=__float_as_uint(bp[4]);
            }
#pragma unroll
            for(int mi=0;mi<2;mi++)
#pragma unroll
                for(int ni=0;ni<4;ni++) mma8(lfr[mi][ni],aQ[ks][mi],bb[ni]);
        }

        // ---- epilogue: e = keep * exp2(l) -> E fp16 smem; register rowsum
        const float* kp=(const float*)(smc+KP_B+cur*256);
#pragma unroll
        for(int mi=0;mi<2;mi++){
            const int r=wm*32+mi*16+g;
#pragma unroll
            for(int ni=0;ni<4;ni++){
                const int col=wn*32+ni*8+t*2;
                const float k0v=kp[col], k1v=kp[col+1];
                float e00=k0v*fexp2(lfr[mi][ni][0]);
                float e01=k1v*fexp2(lfr[mi][ni][1]);
                float e10=k0v*fexp2(lfr[mi][ni][2]);
                float e11=k1v*fexp2(lfr[mi][ni][3]);
                __half2 h0=__floats2half2_rn(e00,e01);
                __half2 h1=__floats2half2_rn(e10,e11);
                *(__half2*)(smc+E_B+((size_t)r*72+col)*2)     = h0;
                *(__half2*)(smc+E_B+((size_t)(r+8)*72+col)*2) = h1;
                rsum[mi][0]+=e00+e01;
                rsum[mi][1]+=e10+e11;
            }
        }
        __syncthreads();                       // E visible

        // ---- PV (fp16 m16n8k16): O += E @ Vt^T
#pragma unroll
        for(int kc=0;kc<4;kc++){
            const int k0=kc*16;
            uint32_t a[2][4], bb[4][2];
#pragma unroll
            for(int mi=0;mi<2;mi++){
                const char* ap = smc+E_B+((size_t)(wm*32+mi*16+g)*72 + k0 + 2*t)*2;
                a[mi][0]=*(const uint32_t*)(ap);
                a[mi][1]=*(const uint32_t*)(ap + 8*72*2);
                a[mi][2]=*(const uint32_t*)(ap + 8*2);
                a[mi][3]=*(const uint32_t*)(ap + (8*72+8)*2);
            }
#pragma unroll
            for(int ni=0;ni<4;ni++){
                const int n=wn*32+ni*8+g;
                const char* bp = smc+V_B+cur*9216+((size_t)n*72 + k0 + 2*t)*2;
                bb[ni][0]=*(const uint32_t*)(bp);
                bb[ni][1]=*(const uint32_t*)(bp + 8*2);
            }
#pragma unroll
            for(int mi=0;mi<2;mi++)
#pragma unroll
                for(int ni=0;ni<4;ni++) mma16h(o[mi][ni],a[mi],bb[ni]);
        }

        // ---- probs store (unnormalized e), coalesced, fp16 -> f32
#pragma unroll
        for(int j=0;j<8;j++){
            int idx = tid + j*128;             // 0..1023
            int row = idx>>4, c4=(idx&15)*4;
            uint32_t w0=*(const uint32_t*)(smc+E_B+((size_t)row*72+c4)*2);
            uint32_t w1=*(const uint32_t*)(smc+E_B+((size_t)row*72+c4+2)*2);
            float2 f0=__half22float2(*(__half2*)&w0);
            float2 f1=__half22float2(*(__half2*)&w1);
            float4 v; v.x=f0.x; v.y=f0.y; v.z=f1.x; v.w=f1.y;
            *(float4*)&outp[(size_t)(kb0+q0+row)*SEQ + (size_t)i*KT2 + c4] = v;
        }
    }

    // ---- deterministic rowsum reduce -> inv
#pragma unroll
    for(int mi=0;mi<2;mi++)
#pragma unroll
        for(int h=0;h<2;h++){
            float v=rsum[mi][h];
            v+=__shfl_xor_sync(0xffffffffu,v,1);
            v+=__shfl_xor_sync(0xffffffffu,v,2);
            if(t==0) rs2[(wm*32+mi*16+h*8+g)*2+wn]=v;
        }
    __syncthreads();
    if(tid<64) invs[tid]=1.0f/(rs2[2*tid]+rs2[2*tid+1]);
    __syncthreads();

    // ---- read output
    {
        float* rout = outp + PROBS_ELEMS;
#pragma unroll
        for(int mi=0;mi<2;mi++){
            const int r=wm*32+mi*16+g;
            const float i0=invs[r], i1=invs[r+8];
#pragma unroll
            for(int ni=0;ni<4;ni++){
                const int col=wn*32+ni*8+t*2;
                size_t o0=(size_t)(kb0+q0+r)*HD+col;
                size_t o1=(size_t)(kb0+q0+r+8)*HD+col;
                rout[o0]  =o[mi][ni][0]*i0;
                rout[o0+1]=o[mi][ni][1]*i0;
                rout[o1]  =o[mi][ni][2]*i1;
                rout[o1+1]=o[mi][ni][3]*i1;
            }
        }
    }

    // ---- folded rescale: this CTA normalizes its own 64 probs rows
    for(int rr=0; rr<16; rr++){
        const int row = wid*16 + rr;
        const float inv = invs[row];
        float4* base = (float4*)&outp[(size_t)(kb0+q0+row)*SEQ];
#pragma unroll 4
        for(int j=0;j<32;j++){
            float4 v = base[lane + j*32];
            v.x*=inv; v.y*=inv; v.z*=inv; v.w*=inv;
            base[lane + j*32] = v;
        }
    }
}

// ---------------------------------------------------------------------------
extern "C" void kernel_launch(void* const* d_in, const int* in_sizes, int n_in,
                              void* d_out, int out_size) {
    const float* x  =(const float*)d_in[0];
    const float* buf=(const float*)d_in[1];
    const void*  msk=d_in[2];
    const float* Wk =(const float*)d_in[3];
    const float* bk =(const float*)d_in[4];
    const float* Wv =(const float*)d_in[5];
    const float* bv =(const float*)d_in[6];
    float* outp=(float*)d_out;

    cudaFuncSetAttribute(proj_kernel, cudaFuncAttributeMaxDynamicSharedMemorySize, PROJ_SMEM_BYTES);
    cudaFuncSetAttribute(attn_kernel, cudaFuncAttributeMaxDynamicSharedMemorySize, ATTN_SMEM);

    proj_kernel<<<512, 256, PROJ_SMEM_BYTES>>>(x, buf, Wk, bk, Wv, bv);
    mask_detect_kernel<<<1, 256>>>((const uint32_t*)msk);
    mask_decode_kernel<<<NROWS/256, 256>>>(msk);
    attn_kernel<<<512, 128, ATTN_SMEM>>>(outp);
}

// round 9
// speedup vs baseline: 1.9634x; 1.2701x over previous
#include <cuda_runtime.h>
#include <cuda_fp16.h>
#include <cstdint>
#include <cstddef>

// ---------------------------------------------------------------------------
// BufferAttend1d (sm_100). B=8, Q=K=4096, DIN=256, d=64.
// Output: probs (8*4096*4096 f32) ++ read (8*4096*64 f32).
//
// All-fp16 operand path (f32 accumulate):
//  proj: x->g_Qh (fp16, pre-scaled log2e/8), buffer->g_Kh (fp16),
//        buffer->g_Vt (fp16, transposed [b*64+vd][seq]).
//  attn: q-tile 128 (256 thr, 8 warps, 2 CTAs/SM), k-tile 64, cp.async
//        double buffered. QK fp16 m16n8k16 (Q smem-resident, K smem) ->
//        e = keep*exp2(l) -> E fp16 smem -> PV fp16 -> O f32 regs.
//        probs <- E (unnormalized, coalesced); register rowsum -> inv;
//        tail: CTA rescales its own 128 probs rows (overlapped chip-wide).
// ---------------------------------------------------------------------------

#define SEQ   4096
#define NB    8
#define DIN   256
#define HD    64
#define NROWS (NB*SEQ)
#define PROBS_ELEMS (8LL*4096LL*4096LL)
#define KT2   64
#define NT2   (SEQ/KT2)    // 64

// attn smem byte offsets (fp16 tiles, row stride 144B = 72 halves)
#define Q_B   0              // 128 x 144                     = 18432
#define E_B   18432          // 128 x 144                     = 18432
#define K_B   36864          // 2 x (64 x 144)                = 18432
#define V_B   55296          // 2 x (64 x 144)                = 18432
#define KP_B  73728          // 2 x 256
#define RS_B  74240          // 128*2*4 = 1024
#define IV_B  75264          // 128*4   = 512
#define ATTN_SMEM 75776

__device__ uint16_t g_Qh[(size_t)NROWS*HD];
__device__ uint16_t g_Kh[(size_t)NROWS*HD];
__device__ uint16_t g_Vt[(size_t)NB*HD*SEQ];   // [b*64+vd][seq]
__device__ float    g_keep[NROWS];
__device__ int      g_mask_fmt;

__device__ __forceinline__ uint32_t f2tf(float x){uint32_t y;asm("cvt.rna.tf32.f32 %0, %1;":"=r"(y):"f"(x));return y;}
__device__ __forceinline__ float fexp2(float x){float y;asm("ex2.approx.f32 %0, %1;":"=f"(y):"f"(x));return y;}
__device__ __forceinline__ uint32_t smem_u32(const void* p){uint32_t a;asm("{ .reg .u64 t; cvta.to.shared.u64 t, %1; cvt.u32.u64 %0, t; }":"=r"(a):"l"(p));return a;}
__device__ __forceinline__ void cpa16(uint32_t s, const void* g){
    asm volatile("cp.async.cg.shared.global [%0], [%1], 16;"::"r"(s),"l"(g));
}
#define CP_COMMIT() asm volatile("cp.async.commit_group;" ::: "memory")
#define CP_WAIT1()  asm volatile("cp.async.wait_group 1;" ::: "memory")
#define CP_WAIT0()  asm volatile("cp.async.wait_group 0;" ::: "memory")

__device__ __forceinline__ void mma8(float* c, const uint32_t* a, const uint32_t* b){
    asm volatile("mma.sync.aligned.m16n8k8.row.col.f32.tf32.tf32.f32 "
        "{%0,%1,%2,%3}, {%4,%5,%6,%7}, {%8,%9}, {%0,%1,%2,%3};\n"
        : "+f"(c[0]),"+f"(c[1]),"+f"(c[2]),"+f"(c[3])
        : "r"(a[0]),"r"(a[1]),"r"(a[2]),"r"(a[3]),"r"(b[0]),"r"(b[1]));
}
__device__ __forceinline__ void mma16h(float* c, const uint32_t* a, const uint32_t* b){
    asm volatile("mma.sync.aligned.m16n8k16.row.col.f32.f16.f16.f32 "
        "{%0,%1,%2,%3}, {%4,%5,%6,%7}, {%8,%9}, {%0,%1,%2,%3};\n"
        : "+f"(c[0]),"+f"(c[1]),"+f"(c[2]),"+f"(c[3])
        : "r"(a[0]),"r"(a[1]),"r"(a[2]),"r"(a[3]),"r"(b[0]),"r"(b[1]));
}
__device__ __forceinline__ void zero4(float a[2][4][4]){
#pragma unroll
    for(int i=0;i<2;i++)
#pragma unroll
        for(int j=0;j<4;j++)
#pragma unroll
            for(int k=0;k<4;k++) a[i][j][k]=0.f;
}

// ---------------- mask ----------------
__global__ void mask_detect_kernel(const uint32_t* __restrict__ mw){
    __shared__ int iok_s, fok_s;
    if(threadIdx.x==0){iok_s=1;fok_s=1;}
    __syncthreads();
    int iok=1, fok=1;
    for(int i=threadIdx.x;i<NROWS/4;i+=blockDim.x){
        uint32_t v=mw[i];
        if(v!=0u&&v!=1u) iok=0;
        if(v!=0u&&v!=0x3F800000u) fok=0;
    }
    if(!iok) atomicExch(&iok_s,0);
    if(!fok) atomicExch(&fok_s,0);
    __syncthreads();
    if(threadIdx.x==0) g_mask_fmt = iok_s?1:(fok_s?2:0);
}
__global__ void mask_decode_kernel(const void* __restrict__ mp){
    int i=blockIdx.x*blockDim.x+threadIdx.x;
    if(i>=NROWS) return;
    int f=g_mask_fmt, m;
    if(f==1) m=((const int*)mp)[i]!=0;
    else if(f==2) m=((const float*)mp)[i]!=0.0f;
    else m=((const unsigned char*)mp)[i]!=0;
    g_keep[i]= m?0.0f:1.0f;
}

// ---------------- projection (tf32 mma, fp16 outputs) ----------------
#define PROJ_SMEM_BYTES ((128*68+64*68)*4)
__global__ __launch_bounds__(256) void proj_kernel(
    const float* __restrict__ x, const float* __restrict__ buf,
    const float* __restrict__ Wk, const float* __restrict__ bk,
    const float* __restrict__ Wv, const float* __restrict__ bv)
{
    extern __shared__ float sm[];
    float* As=sm; float* Ws=sm+128*68;
    const int tid=threadIdx.x, lane=tid&31, wid=tid>>5;
    const int g=lane>>2, t=lane&3, wm=wid&3, wn=wid>>2;
    const bool isx = blockIdx.x<256;
    const int row0=(blockIdx.x&255)*128;
    const float* in = isx?x:buf;
    const int nsweep = isx?1:2;
    const float osc = isx ? 0.125f*1.4426950408889634f : 1.0f;

    for(int sw=0; sw<nsweep; sw++){
        const float* W=(sw==0)?Wk:Wv;
        const float* bias=(sw==0)?bk:bv;
        const int isV = (!isx) && (sw==1);
        float acc[2][4][4];
        zero4(acc);
        for(int kc=0;kc<4;kc++){
            __syncthreads();
            for(int i=tid;i<128*16;i+=256){
                int r=i>>4,c=(i&15)*4;
                *(float4*)&As[r*68+c] = *(const float4*)&in[(size_t)(row0+r)*DIN+kc*64+c];
            }
            for(int i=tid;i<64*16;i+=256){
                int r=i>>4,c=(i&15)*4;
                *(float4*)&Ws[r*68+c] = *(const float4*)&W[(size_t)r*DIN+kc*64+c];
            }
            __syncthreads();
#pragma unroll
            for(int ks=0;ks<8;ks++){
                const int k0=ks*8;
                uint32_t a[2][4], bb[4][2];
#pragma unroll
                for(int mi=0;mi<2;mi++){
                    const float* ap=As+(wm*32+mi*16+g)*68+k0+t;
                    a[mi][0]=f2tf(ap[0]); a[mi][1]=f2tf(ap[8*68]);
                    a[mi][2]=f2tf(ap[4]); a[mi][3]=f2tf(ap[8*68+4]);
                }
#pragma unroll
                for(int ni=0;ni<4;ni++){
                    const float* bp=Ws+(wn*32+ni*8+g)*68+k0+t;
                    bb[ni][0]=f2tf(bp[0]); bb[ni][1]=f2tf(bp[4]);
                }
#pragma unroll
                for(int mi=0;mi<2;mi++)
#pragma unroll
                    for(int ni=0;ni<4;ni++) mma8(acc[mi][ni],a[mi],bb[ni]);
            }
        }
#pragma unroll
        for(int mi=0;mi<2;mi++)
#pragma unroll
            for(int ni=0;ni<4;ni++){
                int r=row0+wm*32+mi*16+g, col=wn*32+ni*8+t*2;
                float b0=__ldg(&bias[col]), b1=__ldg(&bias[col+1]);
                float v00=acc[mi][ni][0]+b0, v01=acc[mi][ni][1]+b1;
                float v10=acc[mi][ni][2]+b0, v11=acc[mi][ni][3]+b1;
                if(isV){
                    int b_  = r>>12,      s0 = r&4095;
                    int b2  = (r+8)>>12,  s1 = (r+8)&4095;
                    g_Vt[((size_t)(b_*64+col  )<<12)+s0]=__half_as_ushort(__float2half_rn(v00));
                    g_Vt[((size_t)(b_*64+col+1)<<12)+s0]=__half_as_ushort(__float2half_rn(v01));
                    g_Vt[((size_t)(b2*64+col  )<<12)+s1]=__half_as_ushort(__float2half_rn(v10));
                    g_Vt[((size_t)(b2*64+col+1)<<12)+s1]=__half_as_ushort(__float2half_rn(v11));
                } else {
                    uint16_t* out = isx ? g_Qh : g_Kh;
                    __half2 h0=__floats2half2_rn(v00*osc, v01*osc);
                    __half2 h1=__floats2half2_rn(v10*osc, v11*osc);
                    *(__half2*)(out+(size_t)r*HD+col)     = h0;
                    *(__half2*)(out+(size_t)(r+8)*HD+col) = h1;
                }
            }
    }
}

// ---------------- attention ----------------
__device__ __forceinline__ void stage_cp(uint32_t sb, int bi, int krg, int b, int k0l, int tid){
    // K tile: 64 keys x 64 kd fp16 (128B/row), smem stride 144B
    const uint32_t kd = sb + K_B + bi*9216;
#pragma unroll
    for(int j=0;j<2;j++){
        int idx = tid + j*256;             // 0..511
        int row = idx>>3, ch = idx&7;
        cpa16(kd + (uint32_t)row*144 + (uint32_t)ch*16,
              (const char*)(g_Kh + (size_t)(krg+row)*HD) + ch*16);
    }
    // Vt tile: 64 vd-rows x 64 keys fp16, smem stride 144B
    const uint32_t vd = sb + V_B + bi*9216;
#pragma unroll
    for(int j=0;j<2;j++){
        int idx = tid + j*256;
        int row = idx>>3, ch = idx&7;
        cpa16(vd + (uint32_t)row*144 + (uint32_t)ch*16,
              (const char*)(g_Vt + ((size_t)(b*64+row)<<12) + k0l) + ch*16);
    }
    if(tid<16) cpa16(sb+KP_B+bi*256+tid*16, (const char*)(g_keep+krg)+tid*16);
}

__global__ __launch_bounds__(256,2) void attn_kernel(float* __restrict__ outp)
{
    extern __shared__ char smc[];
    const uint32_t sb = smem_u32(smc);
    float* rs2 =(float*)(smc+RS_B);
    float* invs=(float*)(smc+IV_B);

    const int tid=threadIdx.x, lane=tid&31, wid=tid>>5;
    const int g=lane>>2, t=lane&3;
    const int wm=wid&3, wn=wid>>2;
    const int b=blockIdx.x>>5, q0=(blockIdx.x&31)*128;
    const int kb0=b<<12;

    // stage Q tile (fp16, pre-scaled) via cp.async
#pragma unroll
    for(int j=0;j<4;j++){
        int idx = tid + j*256;             // 0..1023
        int row = idx>>3, ch = idx&7;
        cpa16(sb+Q_B + (uint32_t)row*144 + (uint32_t)ch*16,
              (const char*)(g_Qh + (size_t)(kb0+q0+row)*HD) + ch*16);
    }
    CP_COMMIT();
    // stage tile 0
    stage_cp(sb, 0, kb0, b, 0, tid);
    CP_COMMIT();

    float o[2][4][4];
    zero4(o);
    float rsum[2][2]={{0.f,0.f},{0.f,0.f}};

    for(int i=0;i<NT2;i++){
        const int cur=i&1;
        __syncthreads();                       // prior readers of buf(cur^1), E done
        if(i+1<NT2){
            stage_cp(sb, cur^1, kb0+(i+1)*KT2, b, (i+1)*KT2, tid);
            CP_COMMIT();
            CP_WAIT1();
        } else {
            CP_WAIT0();
        }
        __syncthreads();                       // Q (iter0) + buf(cur) visible

        // ---- QK (fp16 m16n8k16): lfr = Q @ K^T
        float lfr[2][4][4];
        zero4(lfr);
#pragma unroll
        for(int kc=0;kc<4;kc++){
            const int k0=kc*16;
            uint32_t a[2][4], bb[4][2];
#pragma unroll
            for(int mi=0;mi<2;mi++){
                const char* ap = smc+Q_B + ((size_t)(wm*32+mi*16+g)*72 + k0 + 2*t)*2;
                a[mi][0]=*(const uint32_t*)(ap);
                a[mi][1]=*(const uint32_t*)(ap + 8*144);
                a[mi][2]=*(const uint32_t*)(ap + 16);
                a[mi][3]=*(const uint32_t*)(ap + 8*144+16);
            }
#pragma unroll
            for(int ni=0;ni<4;ni++){
                const char* bp = smc+K_B+cur*9216 + ((size_t)(wn*32+ni*8+g)*72 + k0 + 2*t)*2;
                bb[ni][0]=*(const uint32_t*)(bp);
                bb[ni][1]=*(const uint32_t*)(bp + 16);
            }
#pragma unroll
            for(int mi=0;mi<2;mi++)
#pragma unroll
                for(int ni=0;ni<4;ni++) mma16h(lfr[mi][ni],a[mi],bb[ni]);
        }

        // ---- epilogue: e = keep * exp2(l) -> E fp16; register rowsum
        const float* kp=(const float*)(smc+KP_B+cur*256);
#pragma unroll
        for(int mi=0;mi<2;mi++){
            const int r=wm*32+mi*16+g;
#pragma unroll
            for(int ni=0;ni<4;ni++){
                const int col=wn*32+ni*8+t*2;
                const float k0v=kp[col], k1v=kp[col+1];
                float e00=k0v*fexp2(lfr[mi][ni][0]);
                float e01=k1v*fexp2(lfr[mi][ni][1]);
                float e10=k0v*fexp2(lfr[mi][ni][2]);
                float e11=k1v*fexp2(lfr[mi][ni][3]);
                *(__half2*)(smc+E_B+((size_t)r*72+col)*2)     = __floats2half2_rn(e00,e01);
                *(__half2*)(smc+E_B+((size_t)(r+8)*72+col)*2) = __floats2half2_rn(e10,e11);
                rsum[mi][0]+=e00+e01;
                rsum[mi][1]+=e10+e11;
            }
        }
        __syncthreads();                       // E visible

        // ---- PV (fp16): O += E @ Vt^T
#pragma unroll
        for(int kc=0;kc<4;kc++){
            const int k0=kc*16;
            uint32_t a[2][4], bb[4][2];
#pragma unroll
            for(int mi=0;mi<2;mi++){
                const char* ap = smc+E_B + ((size_t)(wm*32+mi*16+g)*72 + k0 + 2*t)*2;
                a[mi][0]=*(const uint32_t*)(ap);
                a[mi][1]=*(const uint32_t*)(ap + 8*144);
                a[mi][2]=*(const uint32_t*)(ap + 16);
                a[mi][3]=*(const uint32_t*)(ap + 8*144+16);
            }
#pragma unroll
            for(int ni=0;ni<4;ni++){
                const char* bp = smc+V_B+cur*9216 + ((size_t)(wn*32+ni*8+g)*72 + k0 + 2*t)*2;
                bb[ni][0]=*(const uint32_t*)(bp);
                bb[ni][1]=*(const uint32_t*)(bp + 16);
            }
#pragma unroll
            for(int mi=0;mi<2;mi++)
#pragma unroll
                for(int ni=0;ni<4;ni++) mma16h(o[mi][ni],a[mi],bb[ni]);
        }

        // ---- probs store (unnormalized e), coalesced, fp16 -> f32
#pragma unroll
        for(int j=0;j<8;j++){
            int idx = tid + j*256;             // 0..2047
            int row = idx>>4, c4=(idx&15)*4;
            uint32_t w0=*(const uint32_t*)(smc+E_B+((size_t)row*72+c4)*2);
            uint32_t w1=*(const uint32_t*)(smc+E_B+((size_t)row*72+c4+2)*2);
            float2 f0=__half22float2(*(__half2*)&w0);
            float2 f1=__half22float2(*(__half2*)&w1);
            float4 v; v.x=f0.x; v.y=f0.y; v.z=f1.x; v.w=f1.y;
            *(float4*)&outp[(size_t)(kb0+q0+row)*SEQ + (size_t)i*KT2 + c4] = v;
        }
    }

    // ---- deterministic rowsum reduce -> inv
#pragma unroll
    for(int mi=0;mi<2;mi++)
#pragma unroll
        for(int h=0;h<2;h++){
            float v=rsum[mi][h];
            v+=__shfl_xor_sync(0xffffffffu,v,1);
            v+=__shfl_xor_sync(0xffffffffu,v,2);
            if(t==0) rs2[(wm*32+mi*16+h*8+g)*2+wn]=v;
        }
    __syncthreads();
    if(tid<128) invs[tid]=1.0f/(rs2[2*tid]+rs2[2*tid+1]);
    __syncthreads();

    // ---- read output
    {
        float* rout = outp + PROBS_ELEMS;
#pragma unroll
        for(int mi=0;mi<2;mi++){
            const int r=wm*32+mi*16+g;
            const float i0=invs[r], i1=invs[r+8];
#pragma unroll
            for(int ni=0;ni<4;ni++){
                const int col=wn*32+ni*8+t*2;
                size_t o0=(size_t)(kb0+q0+r)*HD+col;
                size_t o1=(size_t)(kb0+q0+r+8)*HD+col;
                rout[o0]  =o[mi][ni][0]*i0;
                rout[o0+1]=o[mi][ni][1]*i0;
                rout[o1]  =o[mi][ni][2]*i1;
                rout[o1+1]=o[mi][ni][3]*i1;
            }
        }
    }

    // ---- folded rescale: this CTA normalizes its own 128 probs rows
    for(int rr=0; rr<16; rr++){
        const int row = wid*16 + rr;
        const float inv = invs[row];
        float4* base = (float4*)&outp[(size_t)(kb0+q0+row)*SEQ];
#pragma unroll 4
        for(int j=0;j<32;j++){
            float4 v = base[lane + j*32];
            v.x*=inv; v.y*=inv; v.z*=inv; v.w*=inv;
            base[lane + j*32] = v;
        }
    }
}

// ---------------------------------------------------------------------------
extern "C" void kernel_launch(void* const* d_in, const int* in_sizes, int n_in,
                              void* d_out, int out_size) {
    const float* x  =(const float*)d_in[0];
    const float* buf=(const float*)d_in[1];
    const void*  msk=d_in[2];
    const float* Wk =(const float*)d_in[3];
    const float* bk =(const float*)d_in[4];
    const float* Wv =(const float*)d_in[5];
    const float* bv =(const float*)d_in[6];
    float* outp=(float*)d_out;

    cudaFuncSetAttribute(proj_kernel, cudaFuncAttributeMaxDynamicSharedMemorySize, PROJ_SMEM_BYTES);
    cudaFuncSetAttribute(attn_kernel, cudaFuncAttributeMaxDynamicSharedMemorySize, ATTN_SMEM);

    proj_kernel<<<512, 256, PROJ_SMEM_BYTES>>>(x, buf, Wk, bk, Wv, bv);
    mask_detect_kernel<<<1, 256>>>((const uint32_t*)msk);
    mask_decode_kernel<<<NROWS/256, 256>>>(msk);
    attn_kernel<<<256, 256, ATTN_SMEM>>>(outp);
}